// round 13
// baseline (speedup 1.0000x reference)
#include <cuda_runtime.h>
#include <cuda_fp16.h>

// out[b,c,h,w] = (Re + Im)( FFT4D(x) ) / 2^26 ; x: [16,64,256,256] f32.
//
// Pipeline:
//  p12: x -> B[ns][bc][w']   (fused real W-FFT (two-for-one) + H-FFT in one
//        130KB smem tile per bc; ns = FFT position, true h = brev8(ns))
//        NOTE: B carries a uniform 2x factor (Hermitian unpack un-halved);
//        compensated by INV_H = INV_N/2 in p3/p3e.
//  p3 : B -> out             (16-pt B-FFT + 64-pt C-FFT + Hermitian-mirror
//                             output, fused; w' 0..127)
//  p3e: w'=128 plane -> out column w=128
#define W2 132
__device__ unsigned int g_B[34603008];   // 1024*256*132 half2

#define INV_H (1.0f / 134217728.0f)      // INV_N * 0.5
#define PI_F 3.14159265358979f

__device__ __forceinline__ float2 cmul(float2 a, float2 b) {
    return make_float2(a.x*b.x - a.y*b.y, a.x*b.y + a.y*b.x);
}
__device__ __forceinline__ float2 cadd(float2 a, float2 b) { return make_float2(a.x+b.x, a.y+b.y); }
__device__ __forceinline__ float2 csub(float2 a, float2 b) { return make_float2(a.x-b.x, a.y-b.y); }
__device__ __forceinline__ float2 Wang(float e, float sc) {   // exp(-i*pi*e*sc), MUFU
    float2 w; __sincosf(-e * sc * PI_F, &w.y, &w.x); return w;
}
__device__ __forceinline__ unsigned int pk(float2 v) {
    __half2 h = __floats2half2_rn(v.x, v.y);
    return *reinterpret_cast<unsigned int*>(&h);
}
__device__ __forceinline__ float2 upk(unsigned int u) {
    __half2 h = *reinterpret_cast<__half2*>(&u);
    return __half22float2(h);
}
__device__ __forceinline__ int brev6(int v) { return (int)(__brev((unsigned)v) >> 26); }
__device__ __forceinline__ int brev8(int v) { return (int)(__brev((unsigned)v) >> 24); }

// W16^e, e = 0..7
__device__ __constant__ float2 T16C[8] = {
    { 1.00000000f,  0.00000000f}, { 0.92387953f, -0.38268343f},
    { 0.70710678f, -0.70710678f}, { 0.38268343f, -0.92387953f},
    { 0.00000000f, -1.00000000f}, {-0.38268343f, -0.92387953f},
    {-0.70710678f, -0.70710678f}, {-0.92387953f, -0.38268343f}};

// ---------------------------------------------------------------------------
// Per-lane twiddle table for the 256-pt warp FFT: TWS[12][32] float2.
// ---------------------------------------------------------------------------
__device__ __forceinline__ void fill_tw256(float2* TWS, int tid) {
    if (tid < 32) {
        const float sc = 1.0f / 128.0f;
        int L = tid;
        TWS[0*32+L] = Wang((float)(L      ), sc);
        TWS[1*32+L] = Wang((float)(L +  32), sc);
        TWS[2*32+L] = Wang((float)(L +  64), sc);
        TWS[3*32+L] = Wang((float)(L +  96), sc);
        TWS[4*32+L] = Wang((float)(2*L    ), sc);
        TWS[5*32+L] = Wang((float)(2*L+ 64), sc);
        TWS[6*32+L] = Wang((float)(4*L    ), sc);
        int s = 7;
#pragma unroll
        for (int m = 16; m >= 1; m >>= 1) {
            TWS[s*32+L] = Wang((float)((L & (m-1)) * (128/m)), sc);
            s++;
        }
    }
}

// Warp-resident 256-pt DIF FFT, twiddles from per-lane smem table.
// Input z[i] = x[lane + 32*i] natural order; output pos n holds X[brev8(n)].
__device__ __forceinline__ void fft256_warp(float2 z[8], const float2* twl) {
#pragma unroll
    for (int i = 0; i < 4; i++) {                       // h = 128
        float2 a = z[i], b = z[i+4];
        z[i]   = cadd(a, b);
        z[i+4] = cmul(twl[i*32], csub(a, b));
    }
    {                                                   // h = 64
        float2 w0 = twl[4*32], w1 = twl[5*32];
        float2 a, b;
        a = z[0]; b = z[2]; z[0] = cadd(a,b); z[2] = cmul(w0, csub(a,b));
        a = z[1]; b = z[3]; z[1] = cadd(a,b); z[3] = cmul(w1, csub(a,b));
        a = z[4]; b = z[6]; z[4] = cadd(a,b); z[6] = cmul(w0, csub(a,b));
        a = z[5]; b = z[7]; z[5] = cadd(a,b); z[7] = cmul(w1, csub(a,b));
    }
    {                                                   // h = 32
        float2 w = twl[6*32];
#pragma unroll
        for (int i = 0; i < 8; i += 2) {
            float2 a = z[i], b = z[i+1];
            z[i]   = cadd(a, b);
            z[i+1] = cmul(w, csub(a, b));
        }
    }
    int s = 7;
    int lane = threadIdx.x & 31;
#pragma unroll
    for (int m = 16; m >= 1; m >>= 1) {                 // cross-lane stages
        float2 w = twl[s*32]; s++;
        bool hi = (lane & m) != 0;
#pragma unroll
        for (int i = 0; i < 8; i++) {
            float2 o;
            o.x = __shfl_xor_sync(0xffffffffu, z[i].x, m);
            o.y = __shfl_xor_sync(0xffffffffu, z[i].y, m);
            if (hi) z[i] = cmul(w, csub(o, z[i]));
            else    z[i] = cadd(z[i], o);
        }
    }
}

// 16-pt DIF; position p holds spectrum index brev4(p).
__device__ __forceinline__ void dif16(float2 r[16]) {
#pragma unroll
    for (int h = 8; h >= 1; h >>= 1) {
#pragma unroll
        for (int base = 0; base < 16; base += 2*h) {
#pragma unroll
            for (int j = 0; j < h; j++) {
                float2 a = r[base+j], b = r[base+j+h];
                r[base+j]   = cadd(a, b);
                r[base+j+h] = cmul(T16C[j * (8/h)], csub(a, b));
            }
        }
    }
}

// Column swizzle for the p12 tile: spreads brev-pattern columns over banks.
#define SWC(c) ((c) ^ (((c) >> 5) & 7))

// ---------------------------------------------------------------------------
// p12: fused W-FFT + H-FFT for one bc plane. 1024 threads.
// Smem: T[128][259] packed half2 (129.5KB) + TWS (3KB).
// ---------------------------------------------------------------------------
#define TP 259
__global__ void __launch_bounds__(1024) p12_kernel(const float* __restrict__ x) {
    extern __shared__ unsigned int T[];   // [128][TP] then TWS
    float2* TWS = (float2*)(T + 128 * TP);
    int tid  = threadIdx.x;
    int lane = tid & 31, wp = tid >> 5;   // 32 warps
    int bc = blockIdx.x;

    fill_tw256(TWS, tid);
    __syncthreads();
    const float2* twl = TWS + lane;

    // W-phase: 128 two-for-one FFTs (pair p = rows 2p,2p+1 packed re/im).
#pragma unroll
    for (int it = 0; it < 4; it++) {
        int p = wp + 32*it;
        const float* r0 = x + ((size_t)bc * 256 + 2*p) * 256;
        float2 z[8];
#pragma unroll
        for (int i = 0; i < 8; i++) {
            int n = lane + 32*i;
            z[i] = make_float2(r0[n], r0[256 + n]);
        }
        fft256_warp(z, twl);
#pragma unroll
        for (int i = 0; i < 8; i++)
            T[p * TP + SWC(lane + 32*i)] = pk(z[i]);
    }
    __syncthreads();

    // H-phase: 129 column tasks over 32 warps (warp 0 also takes task 128).
    // Unpack WITHOUT the 0.5 factor (uniform 2x carried into B).
    for (int it = 0; it < 5; it++) {
        int wq = wp + 32*it;
        if (wq > 128) break;
        int q1 = SWC(brev8(wq));
        int q2 = (wq == 0) ? q1 : SWC(brev8(256 - wq));
        float2 z[8];
#pragma unroll
        for (int i = 0; i < 8; i++) {
            int h  = lane + 32*i;
            int pr = h >> 1;
            float2 Z1 = upk(T[pr * TP + q1]);
            float2 Z2 = upk(T[pr * TP + q2]);
            if (h & 1) z[i] = make_float2(Z1.y + Z2.y, Z2.x - Z1.x);
            else       z[i] = make_float2(Z1.x + Z2.x, Z1.y - Z2.y);
        }
        fft256_warp(z, twl);
        int cq2 = (wq == 0) ? 256 : (wq == 128 ? 257 : q2);
#pragma unroll
        for (int i = 0; i < 4; i++)
            T[(lane + 32*i) * TP + q1] = pk(z[i]);
#pragma unroll
        for (int i = 4; i < 8; i++)
            T[(lane + 32*(i-4)) * TP + cq2] = pk(z[i]);
    }
    __syncthreads();

    // Store phase: group g (of 8) owns a contiguous 32-row band, so the
    // low/high-half source-column select is uniform and hoisted.
    {
        int wq  = tid & 127;
        int grp = tid >> 7;                 // 0..7
        bool lowhalf = grp < 4;
        int row0 = (grp & 3) * 32;
        int q1  = SWC(brev8(wq));
        int q2s = (wq == 0) ? 256 : SWC(brev8(256 - wq));
        int srcq = lowhalf ? q1 : q2s;
        int nsbase = lowhalf ? row0 : row0 + 128;
        unsigned int* dst = g_B + ((size_t)nsbase * 1024 + bc) * W2 + wq;
        const unsigned int* srcT = T + row0 * TP + srcq;
#pragma unroll
        for (int j = 0; j < 32; j++)
            dst[(size_t)j * 1024 * W2] = srcT[j * TP];
        if (wq == 0) {                      // w'=128 column (8 threads)
            int sq = lowhalf ? SWC(1) : 257;
            unsigned int* dst2 = g_B + ((size_t)nsbase * 1024 + bc) * W2 + 128;
            const unsigned int* s2 = T + row0 * TP + sq;
#pragma unroll
            for (int j = 0; j < 32; j++)
                dst2[(size_t)j * 1024 * W2] = s2[j * TP];
        }
    }
}

// ---------------------------------------------------------------------------
// p3: FUSED (B,C)-FFT + output, w' 0..127. Block = (stored h, 8-w'-chunk).
// 512 threads, S[1024][9] float2 (72KB) + TWS3 (1.5KB) -> 2 CTAs/SM.
// ---------------------------------------------------------------------------
#define SR 9
__global__ void __launch_bounds__(512) p3_kernel(float* __restrict__ out) {
    extern __shared__ float2 S[];   // [1024][SR] then TWS3[6][32]
    float2* TWS3 = S + 1024 * SR;
    int tid = threadIdx.x;
    int ch = blockIdx.x & 15;
    int hs = blockIdx.x >> 4;
    int w0 = ch << 3;
    int w  = tid & 7;
    int c  = tid >> 3;              // 0..63

    if (tid < 32) {                 // 64-pt FFT twiddle table
        const float sc = 1.0f / 32.0f;
        int L = tid;
        TWS3[0*32+L] = Wang((float)L, sc);
        int s = 1;
#pragma unroll
        for (int m = 16; m >= 1; m >>= 1) {
            TWS3[s*32+L] = Wang((float)((L & (m-1)) * (32/m)), sc);
            s++;
        }
    }

    // Phase A: 16-pt b-FFT straight from global (coalesced reads).
    {
        const unsigned int* Bb = g_B + (size_t)hs * 1024 * W2 + w0 + w;
        float2 r[16];
#pragma unroll
        for (int b = 0; b < 16; b++) r[b] = upk(Bb[(size_t)(b*64 + c) * W2]);
        dif16(r);
#pragma unroll
        for (int p = 0; p < 16; p++) S[(p*64 + c)*SR + w] = r[p];
    }
    __syncthreads();

    // Phase B: 64-pt c-FFT; warp p owns rows [p*64, p*64+64), cols w0..w0+7.
    int lane = tid & 31;
    int p    = tid >> 5;            // 0..15
    const float2* tw3 = TWS3 + lane;
    float2 tw32 = tw3[0];
#pragma unroll
    for (int wg = 0; wg < 2; wg++) {
        float2 z0[4], z1[4];
#pragma unroll
        for (int k = 0; k < 4; k++) {
            z0[k] = S[(p*64 + lane)*SR      + wg*4 + k];
            z1[k] = S[(p*64 + lane + 32)*SR + wg*4 + k];
        }
#pragma unroll
        for (int k = 0; k < 4; k++) {   // h = 32 register stage
            float2 a = z0[k], b = z1[k];
            z0[k] = cadd(a, b);
            z1[k] = cmul(tw32, csub(a, b));
        }
        int s = 1;
#pragma unroll
        for (int m = 16; m >= 1; m >>= 1) {
            float2 tw = tw3[s*32]; s++;
            bool hi = (lane & m) != 0;
#pragma unroll
            for (int k = 0; k < 4; k++) {
                float2 o;
                o.x = __shfl_xor_sync(0xffffffffu, z0[k].x, m);
                o.y = __shfl_xor_sync(0xffffffffu, z0[k].y, m);
                z0[k] = hi ? cmul(tw, csub(o, z0[k])) : cadd(z0[k], o);
                o.x = __shfl_xor_sync(0xffffffffu, z1[k].x, m);
                o.y = __shfl_xor_sync(0xffffffffu, z1[k].y, m);
                z1[k] = hi ? cmul(tw, csub(o, z1[k])) : cadd(z1[k], o);
            }
        }
#pragma unroll
        for (int k = 0; k < 4; k++) {
            S[(p*64 + lane)*SR      + wg*4 + k] = z0[k];
            S[(p*64 + lane + 32)*SR + wg*4 + k] = z1[k];
        }
    }
    __syncthreads();

    // Phase C: output. Base-pointer + immediate-offset addressing:
    // direct  = base1 + b  * 2^22 elements, b  = brev4(j) (compile-time)
    // mirror  = base2 + bm * 2^22 elements, bm = (16-b)&15
    int h  = brev8(hs);
    int hm = (256 - h) & 255;
    int wv = w0 + w;
    int ct = brev6(c);
    int cm = (64 - ct) & 63;
    float* base1 = out + (size_t)ct * 65536 + h * 256 + wv;
    float* base2 = out + (size_t)cm * 65536 + hm * 256 + (256 - wv);
    const float2* Sc = S + c * SR + w;
    constexpr int BR4[16] = {0,8,4,12,2,10,6,14,1,9,5,13,3,11,7,15};
#pragma unroll
    for (int j = 0; j < 16; j++) {
        const int b  = BR4[j];
        const int bm = (16 - b) & 15;
        float2 v = Sc[j * 64 * SR];
        base1[(size_t)b << 22] = (v.x + v.y) * INV_H;
        if (wv >= 1)
            base2[(size_t)bm << 22] = (v.x - v.y) * INV_H;
    }
}

// p3e: (B,C)-FFT + output for the w'=128 plane (self-mirror column).
__global__ void __launch_bounds__(128) p3e_kernel(float* __restrict__ out) {
    __shared__ float2 S[1024];
    int tid = threadIdx.x;
    int hs = blockIdx.x;

    for (int idx = tid; idx < 1024; idx += 128)
        S[idx] = upk(g_B[((size_t)hs * 1024 + idx) * W2 + 128]);
    __syncthreads();

    if (tid < 64) {
        float2 r[16];
#pragma unroll
        for (int b = 0; b < 16; b++) r[b] = S[b*64 + tid];
        dif16(r);
#pragma unroll
        for (int p = 0; p < 16; p++) S[p*64 + tid] = r[p];
    }
    __syncthreads();

    int lane = tid & 31;
    int h = brev8(hs);
    const float sc = 1.0f / 32.0f;
    constexpr int BR4[16] = {0,8,4,12,2,10,6,14,1,9,5,13,3,11,7,15};
#pragma unroll
    for (int it = 0; it < 4; it++) {
        int p = (tid >> 5) + 4*it;
        float2 z0 = S[p*64 + lane];
        float2 z1 = S[p*64 + lane + 32];
        {
            float2 tw = Wang((float)lane, sc);
            float2 a = z0, b = z1;
            z0 = cadd(a, b);
            z1 = cmul(tw, csub(a, b));
        }
#pragma unroll
        for (int m = 16; m >= 1; m >>= 1) {
            float2 tw = Wang((float)((lane & (m-1)) * (32/m)), sc);
            bool hi = (lane & m) != 0;
            float2 o;
            o.x = __shfl_xor_sync(0xffffffffu, z0.x, m);
            o.y = __shfl_xor_sync(0xffffffffu, z0.y, m);
            z0 = hi ? cmul(tw, csub(o, z0)) : cadd(z0, o);
            o.x = __shfl_xor_sync(0xffffffffu, z1.x, m);
            o.y = __shfl_xor_sync(0xffffffffu, z1.y, m);
            z1 = hi ? cmul(tw, csub(o, z1)) : cadd(z1, o);
        }
        int b = BR4[p & 15];
        int c0t = brev6(lane);
        int c1t = brev6(lane + 32);
        out[((size_t)((b << 6) | c0t) * 256 + h) * 256 + 128] = (z0.x + z0.y) * INV_H;
        out[((size_t)((b << 6) | c1t) * 256 + h) * 256 + 128] = (z1.x + z1.y) * INV_H;
    }
}

// ---------------------------------------------------------------------------
extern "C" void kernel_launch(void* const* d_in, const int* in_sizes, int n_in,
                              void* d_out, int out_size) {
    (void)in_sizes; (void)n_in; (void)out_size;
    const float* x = (const float*)d_in[0];
    float* out = (float*)d_out;

    const int P12_SMEM = 128 * TP * (int)sizeof(unsigned int) + 12 * 32 * (int)sizeof(float2);
    const int P3_SMEM  = 1024 * SR * (int)sizeof(float2) + 6 * 32 * (int)sizeof(float2);

    static int smem_set = 0;
    if (!smem_set) {
        cudaFuncSetAttribute(p12_kernel,
                             cudaFuncAttributeMaxDynamicSharedMemorySize, P12_SMEM);
        cudaFuncSetAttribute(p3_kernel,
                             cudaFuncAttributeMaxDynamicSharedMemorySize, P3_SMEM);
        smem_set = 1;
    }

    p12_kernel<<<1024, 1024, P12_SMEM>>>(x);
    p3_kernel<<<4096, 512, P3_SMEM>>>(out);
    p3e_kernel<<<256, 128>>>(out);
}

// round 14
// speedup vs baseline: 1.1416x; 1.1416x over previous
#include <cuda_runtime.h>
#include <cuda_fp16.h>

// out[b,c,h,w] = (Re + Im)( FFT4D(x) ) / 2^26 ; x: [16,64,256,256] f32.
//
// Pipeline:
//  p12: x -> B[ns][bc][w']   (fused real W-FFT (two-for-one) + H-FFT in one
//        130KB smem tile per bc; ns = FFT position, true h = brev8(ns))
//        B carries a uniform 2x factor; compensated by INV_H in p3/p3e.
//  p3 : B -> out             (16-pt B-FFT + 64-pt C-FFT + Hermitian-mirror
//                             output, fused; w' 0..127)
//  p3e: w'=128 plane -> out column w=128
#define W2 132
__device__ unsigned int g_B[34603008];   // 1024*256*132 half2

#define INV_H (1.0f / 134217728.0f)      // (1/2^26) * 0.5
#define PI_F 3.14159265358979f

__device__ __forceinline__ float2 cmul(float2 a, float2 b) {
    return make_float2(a.x*b.x - a.y*b.y, a.x*b.y + a.y*b.x);
}
__device__ __forceinline__ float2 cadd(float2 a, float2 b) { return make_float2(a.x+b.x, a.y+b.y); }
__device__ __forceinline__ float2 csub(float2 a, float2 b) { return make_float2(a.x-b.x, a.y-b.y); }
__device__ __forceinline__ float2 Wang(float e, float sc) {   // exp(-i*pi*e*sc), MUFU
    float2 w; __sincosf(-e * sc * PI_F, &w.y, &w.x); return w;
}
__device__ __forceinline__ unsigned int pk(float2 v) {
    __half2 h = __floats2half2_rn(v.x, v.y);
    return *reinterpret_cast<unsigned int*>(&h);
}
__device__ __forceinline__ float2 upk(unsigned int u) {
    __half2 h = *reinterpret_cast<__half2*>(&u);
    return __half22float2(h);
}
__device__ __forceinline__ int brev4(int v) { return (int)(__brev((unsigned)v) >> 28); }
__device__ __forceinline__ int brev6(int v) { return (int)(__brev((unsigned)v) >> 26); }
__device__ __forceinline__ int brev8(int v) { return (int)(__brev((unsigned)v) >> 24); }

// W16^e, e = 0..7
__device__ __constant__ float2 T16C[8] = {
    { 1.00000000f,  0.00000000f}, { 0.92387953f, -0.38268343f},
    { 0.70710678f, -0.70710678f}, { 0.38268343f, -0.92387953f},
    { 0.00000000f, -1.00000000f}, {-0.38268343f, -0.92387953f},
    {-0.70710678f, -0.70710678f}, {-0.92387953f, -0.38268343f}};

// ---------------------------------------------------------------------------
// Per-lane twiddle table for the 256-pt warp FFT: TWS[12][32] float2.
// Stages 7..11 (cross-lane m=16..1) use the UNIFIED butterfly: lo lanes
// ((lane&m)==0) store (1,0); hi lanes store W256^((lane&(m-1))*(128/m)).
// ---------------------------------------------------------------------------
__device__ __forceinline__ void fill_tw256(float2* TWS, int tid) {
    if (tid < 32) {
        const float sc = 1.0f / 128.0f;
        int L = tid;
        TWS[0*32+L] = Wang((float)(L      ), sc);
        TWS[1*32+L] = Wang((float)(L +  32), sc);
        TWS[2*32+L] = Wang((float)(L +  64), sc);
        TWS[3*32+L] = Wang((float)(L +  96), sc);
        TWS[4*32+L] = Wang((float)(2*L    ), sc);
        TWS[5*32+L] = Wang((float)(2*L+ 64), sc);
        TWS[6*32+L] = Wang((float)(4*L    ), sc);
        int s = 7;
#pragma unroll
        for (int m = 16; m >= 1; m >>= 1) {
            TWS[s*32+L] = (L & m) ? Wang((float)((L & (m-1)) * (128/m)), sc)
                                  : make_float2(1.0f, 0.0f);
            s++;
        }
    }
}

// Warp-resident 256-pt DIF FFT, twiddles from per-lane smem table.
// Input z[i] = x[lane + 32*i] natural order; output pos n holds X[brev8(n)].
// Cross-lane stages: branchless r = o + sgn*z; z = tw_eff * r.
__device__ __forceinline__ void fft256_warp(float2 z[8], const float2* twl) {
#pragma unroll
    for (int i = 0; i < 4; i++) {                       // h = 128
        float2 a = z[i], b = z[i+4];
        z[i]   = cadd(a, b);
        z[i+4] = cmul(twl[i*32], csub(a, b));
    }
    {                                                   // h = 64
        float2 w0 = twl[4*32], w1 = twl[5*32];
        float2 a, b;
        a = z[0]; b = z[2]; z[0] = cadd(a,b); z[2] = cmul(w0, csub(a,b));
        a = z[1]; b = z[3]; z[1] = cadd(a,b); z[3] = cmul(w1, csub(a,b));
        a = z[4]; b = z[6]; z[4] = cadd(a,b); z[6] = cmul(w0, csub(a,b));
        a = z[5]; b = z[7]; z[5] = cadd(a,b); z[7] = cmul(w1, csub(a,b));
    }
    {                                                   // h = 32
        float2 w = twl[6*32];
#pragma unroll
        for (int i = 0; i < 8; i += 2) {
            float2 a = z[i], b = z[i+1];
            z[i]   = cadd(a, b);
            z[i+1] = cmul(w, csub(a, b));
        }
    }
    int s = 7;
    int lane = threadIdx.x & 31;
#pragma unroll
    for (int m = 16; m >= 1; m >>= 1) {                 // cross-lane stages
        float2 w = twl[s*32]; s++;
        float sgn = (lane & m) ? -1.0f : 1.0f;
#pragma unroll
        for (int i = 0; i < 8; i++) {
            float2 o;
            o.x = __shfl_xor_sync(0xffffffffu, z[i].x, m);
            o.y = __shfl_xor_sync(0xffffffffu, z[i].y, m);
            float2 r = make_float2(fmaf(sgn, z[i].x, o.x),
                                   fmaf(sgn, z[i].y, o.y));
            z[i] = cmul(w, r);
        }
    }
}

// 16-pt DIF; position p holds spectrum index brev4(p).
__device__ __forceinline__ void dif16(float2 r[16]) {
#pragma unroll
    for (int h = 8; h >= 1; h >>= 1) {
#pragma unroll
        for (int base = 0; base < 16; base += 2*h) {
#pragma unroll
            for (int j = 0; j < h; j++) {
                float2 a = r[base+j], b = r[base+j+h];
                r[base+j]   = cadd(a, b);
                r[base+j+h] = cmul(T16C[j * (8/h)], csub(a, b));
            }
        }
    }
}

// Column swizzle for the p12 tile: spreads brev-pattern columns over banks.
#define SWC(c) ((c) ^ (((c) >> 5) & 7))

// ---------------------------------------------------------------------------
// p12: fused W-FFT + H-FFT for one bc plane. 1024 threads.
// Smem: T[128][259] packed half2 (129.5KB) + TWS (3KB).
// ---------------------------------------------------------------------------
#define TP 259
__global__ void __launch_bounds__(1024) p12_kernel(const float* __restrict__ x) {
    extern __shared__ unsigned int T[];   // [128][TP] then TWS
    float2* TWS = (float2*)(T + 128 * TP);
    int tid  = threadIdx.x;
    int lane = tid & 31, wp = tid >> 5;   // 32 warps
    int bc = blockIdx.x;

    fill_tw256(TWS, tid);
    __syncthreads();
    const float2* twl = TWS + lane;

    // W-phase: 128 two-for-one FFTs (pair p = rows 2p,2p+1 packed re/im).
#pragma unroll
    for (int it = 0; it < 4; it++) {
        int p = wp + 32*it;
        const float* r0 = x + ((size_t)bc * 256 + 2*p) * 256;
        float2 z[8];
#pragma unroll
        for (int i = 0; i < 8; i++) {
            int n = lane + 32*i;
            z[i] = make_float2(r0[n], r0[256 + n]);
        }
        fft256_warp(z, twl);
#pragma unroll
        for (int i = 0; i < 8; i++)
            T[p * TP + SWC(lane + 32*i)] = pk(z[i]);
    }
    __syncthreads();

    // H-phase: 129 column tasks over 32 warps (warp 0 also takes task 128).
    // Unpack WITHOUT the 0.5 factor (uniform 2x carried into B).
    for (int it = 0; it < 5; it++) {
        int wq = wp + 32*it;
        if (wq > 128) break;
        int q1 = SWC(brev8(wq));
        int q2 = (wq == 0) ? q1 : SWC(brev8(256 - wq));
        float2 z[8];
#pragma unroll
        for (int i = 0; i < 8; i++) {
            int h  = lane + 32*i;
            int pr = h >> 1;
            float2 Z1 = upk(T[pr * TP + q1]);
            float2 Z2 = upk(T[pr * TP + q2]);
            if (h & 1) z[i] = make_float2(Z1.y + Z2.y, Z2.x - Z1.x);
            else       z[i] = make_float2(Z1.x + Z2.x, Z1.y - Z2.y);
        }
        fft256_warp(z, twl);
        int cq2 = (wq == 0) ? 256 : (wq == 128 ? 257 : q2);
#pragma unroll
        for (int i = 0; i < 4; i++)
            T[(lane + 32*i) * TP + q1] = pk(z[i]);
#pragma unroll
        for (int i = 4; i < 8; i++)
            T[(lane + 32*(i-4)) * TP + cq2] = pk(z[i]);
    }
    __syncthreads();

    // Store phase (R12 form): group g (of 8) handles rows ns = g+8j.
    {
        int wq = tid & 127;
        int g  = tid >> 7;
        int q1  = SWC(brev8(wq));
        int q2s = (wq == 0) ? 256 : SWC(brev8(256 - wq));
        unsigned int* dB = g_B + bc * (size_t)W2;
#pragma unroll
        for (int j = 0; j < 32; j++) {
            int ns = g + 8*j;
            unsigned int v = (ns < 128) ? T[ns * TP + q1]
                                        : T[(ns - 128) * TP + q2s];
            dB[(size_t)ns * 1024 * W2 + wq] = v;
            if (wq == 0) {   // w'=128 column
                unsigned int v2 = (ns < 128) ? T[ns * TP + SWC(1)]
                                             : T[(ns - 128) * TP + 257];
                dB[(size_t)ns * 1024 * W2 + 128] = v2;
            }
        }
    }
}

// ---------------------------------------------------------------------------
// p3: FUSED (B,C)-FFT + output, w' 0..127. Block = (stored h, 8-w'-chunk).
// 512 threads, S[1024][9] float2 (72KB) + TWS3 (1.5KB) -> 2 CTAs/SM.
// ---------------------------------------------------------------------------
#define SR 9
__global__ void __launch_bounds__(512) p3_kernel(float* __restrict__ out) {
    extern __shared__ float2 S[];   // [1024][SR] then TWS3[6][32]
    float2* TWS3 = S + 1024 * SR;
    int tid = threadIdx.x;
    int ch = blockIdx.x & 15;
    int hs = blockIdx.x >> 4;
    int w0 = ch << 3;
    int w  = tid & 7;
    int c  = tid >> 3;              // 0..63

    if (tid < 32) {                 // 64-pt FFT twiddle table (unified form)
        const float sc = 1.0f / 32.0f;
        int L = tid;
        TWS3[0*32+L] = Wang((float)L, sc);
        int s = 1;
#pragma unroll
        for (int m = 16; m >= 1; m >>= 1) {
            TWS3[s*32+L] = (L & m) ? Wang((float)((L & (m-1)) * (32/m)), sc)
                                   : make_float2(1.0f, 0.0f);
            s++;
        }
    }

    // Phase A: 16-pt b-FFT straight from global (coalesced reads).
    {
        const unsigned int* Bb = g_B + (size_t)hs * 1024 * W2 + w0 + w;
        float2 r[16];
#pragma unroll
        for (int b = 0; b < 16; b++) r[b] = upk(Bb[(size_t)(b*64 + c) * W2]);
        dif16(r);
#pragma unroll
        for (int p = 0; p < 16; p++) S[(p*64 + c)*SR + w] = r[p];
    }
    __syncthreads();

    // Phase B: 64-pt c-FFT; warp p owns rows [p*64, p*64+64), cols w0..w0+7.
    int lane = tid & 31;
    int p    = tid >> 5;            // 0..15
    const float2* tw3 = TWS3 + lane;
    float2 tw32 = tw3[0];
#pragma unroll
    for (int wg = 0; wg < 2; wg++) {
        float2 z0[4], z1[4];
#pragma unroll
        for (int k = 0; k < 4; k++) {
            z0[k] = S[(p*64 + lane)*SR      + wg*4 + k];
            z1[k] = S[(p*64 + lane + 32)*SR + wg*4 + k];
        }
#pragma unroll
        for (int k = 0; k < 4; k++) {   // h = 32 register stage
            float2 a = z0[k], b = z1[k];
            z0[k] = cadd(a, b);
            z1[k] = cmul(tw32, csub(a, b));
        }
        int s = 1;
#pragma unroll
        for (int m = 16; m >= 1; m >>= 1) {
            float2 tw = tw3[s*32]; s++;
            float sgn = (lane & m) ? -1.0f : 1.0f;
#pragma unroll
            for (int k = 0; k < 4; k++) {
                float2 o, r;
                o.x = __shfl_xor_sync(0xffffffffu, z0[k].x, m);
                o.y = __shfl_xor_sync(0xffffffffu, z0[k].y, m);
                r = make_float2(fmaf(sgn, z0[k].x, o.x), fmaf(sgn, z0[k].y, o.y));
                z0[k] = cmul(tw, r);
                o.x = __shfl_xor_sync(0xffffffffu, z1[k].x, m);
                o.y = __shfl_xor_sync(0xffffffffu, z1[k].y, m);
                r = make_float2(fmaf(sgn, z1[k].x, o.x), fmaf(sgn, z1[k].y, o.y));
                z1[k] = cmul(tw, r);
            }
        }
#pragma unroll
        for (int k = 0; k < 4; k++) {
            S[(p*64 + lane)*SR      + wg*4 + k] = z0[k];
            S[(p*64 + lane + 32)*SR + wg*4 + k] = z1[k];
        }
    }
    __syncthreads();

    // Phase C: output. row = c + 64*j -> b = brev4(j), true c = brev6(c).
    int h  = brev8(hs);
    int hm = (256 - h) & 255;
    int wv = w0 + w;
    int ct = brev6(c);
#pragma unroll
    for (int j = 0; j < 16; j++) {
        int row = c + 64*j;
        int b = brev4(j);
        float2 v = S[row*SR + w];
        out[((size_t)((b << 6) | ct) * 256 + h) * 256 + wv] = (v.x + v.y) * INV_H;
        if (wv >= 1) {
            int bcm = (((16 - b) & 15) << 6) | ((64 - ct) & 63);
            out[((size_t)bcm * 256 + hm) * 256 + (256 - wv)] = (v.x - v.y) * INV_H;
        }
    }
}

// p3e: (B,C)-FFT + output for the w'=128 plane (self-mirror column).
__global__ void __launch_bounds__(128) p3e_kernel(float* __restrict__ out) {
    __shared__ float2 S[1024];
    int tid = threadIdx.x;
    int hs = blockIdx.x;

    for (int idx = tid; idx < 1024; idx += 128)
        S[idx] = upk(g_B[((size_t)hs * 1024 + idx) * W2 + 128]);
    __syncthreads();

    if (tid < 64) {
        float2 r[16];
#pragma unroll
        for (int b = 0; b < 16; b++) r[b] = S[b*64 + tid];
        dif16(r);
#pragma unroll
        for (int p = 0; p < 16; p++) S[p*64 + tid] = r[p];
    }
    __syncthreads();

    int lane = tid & 31;
    int h = brev8(hs);
    const float sc = 1.0f / 32.0f;
#pragma unroll
    for (int it = 0; it < 4; it++) {
        int p = (tid >> 5) + 4*it;
        float2 z0 = S[p*64 + lane];
        float2 z1 = S[p*64 + lane + 32];
        {
            float2 tw = Wang((float)lane, sc);
            float2 a = z0, b = z1;
            z0 = cadd(a, b);
            z1 = cmul(tw, csub(a, b));
        }
#pragma unroll
        for (int m = 16; m >= 1; m >>= 1) {
            float2 tw = Wang((float)((lane & (m-1)) * (32/m)), sc);
            bool hi = (lane & m) != 0;
            float2 o;
            o.x = __shfl_xor_sync(0xffffffffu, z0.x, m);
            o.y = __shfl_xor_sync(0xffffffffu, z0.y, m);
            z0 = hi ? cmul(tw, csub(o, z0)) : cadd(z0, o);
            o.x = __shfl_xor_sync(0xffffffffu, z1.x, m);
            o.y = __shfl_xor_sync(0xffffffffu, z1.y, m);
            z1 = hi ? cmul(tw, csub(o, z1)) : cadd(z1, o);
        }
        int b = brev4(p);
        int c0t = brev6(lane);
        int c1t = brev6(lane + 32);
        out[((size_t)((b << 6) | c0t) * 256 + h) * 256 + 128] = (z0.x + z0.y) * INV_H;
        out[((size_t)((b << 6) | c1t) * 256 + h) * 256 + 128] = (z1.x + z1.y) * INV_H;
    }
}

// ---------------------------------------------------------------------------
extern "C" void kernel_launch(void* const* d_in, const int* in_sizes, int n_in,
                              void* d_out, int out_size) {
    (void)in_sizes; (void)n_in; (void)out_size;
    const float* x = (const float*)d_in[0];
    float* out = (float*)d_out;

    const int P12_SMEM = 128 * TP * (int)sizeof(unsigned int) + 12 * 32 * (int)sizeof(float2);
    const int P3_SMEM  = 1024 * SR * (int)sizeof(float2) + 6 * 32 * (int)sizeof(float2);

    static int smem_set = 0;
    if (!smem_set) {
        cudaFuncSetAttribute(p12_kernel,
                             cudaFuncAttributeMaxDynamicSharedMemorySize, P12_SMEM);
        cudaFuncSetAttribute(p3_kernel,
                             cudaFuncAttributeMaxDynamicSharedMemorySize, P3_SMEM);
        smem_set = 1;
    }

    p12_kernel<<<1024, 1024, P12_SMEM>>>(x);
    p3_kernel<<<4096, 512, P3_SMEM>>>(out);
    p3e_kernel<<<256, 128>>>(out);
}